// round 4
// baseline (speedup 1.0000x reference)
#include <cuda_runtime.h>

#define TILE 32
#define RAD 5
#define LT 42            // TILE + 2*RAD
#define IP 43            // staged-array pitch (floats); 43 mod 32 = 11 -> conflict-free h reads
#define HP 33            // h-result pitch (floats); odd -> conflict-free STS + v reads
#define IMG 512
#define NT 256
#define GRID1D 16
#define NBLK (GRID1D * GRID1D * 96)

__device__ float g_part[NBLK];
__device__ int   g_ticket;

__global__ __launch_bounds__(NT) void ssim_kernel(
        const float* __restrict__ A, const float* __restrict__ B,
        float* __restrict__ out, int nblk, float inv_n) {
    // Gaussian(sigma=1.5, 11 taps) -> FFMA-imm (rt=1)
    constexpr float WGT[11] = {
        0.00102836f, 0.00759876f, 0.03600077f, 0.10936070f, 0.21300554f,
        0.26601172f,
        0.21300554f, 0.10936070f, 0.03600077f, 0.00759876f, 0.00102836f };

    __shared__ float sP[LT * IP];
    __shared__ float sQ[LT * IP];
    __shared__ float hP[LT * HP];   // conv_h(p)
    __shared__ float hQ[LT * HP];   // conv_h(q)
    __shared__ float hS[LT * HP];   // conv_h(p^2)
    __shared__ float hD[LT * HP];   // conv_h(q^2)
    __shared__ float wsum[NT / 32];
    __shared__ int   sLast;
    __shared__ double sred[NT];

    const int tid = threadIdx.x;
    const int x0 = blockIdx.x * TILE - RAD;
    const int y0 = blockIdx.y * TILE - RAD;
    const size_t planeOff = (size_t)blockIdx.z * (IMG * IMG);
    const float* __restrict__ pa = A + planeOff;
    const float* __restrict__ pb = B + planeOff;

    // ---- stage (p,q) = (x+y, x-y), zero-padded halo ----
    for (int i = tid; i < LT * LT; i += NT) {
        int r = i / LT;
        int c = i - r * LT;
        int gy = y0 + r, gx = x0 + c;
        float va = 0.f, vb = 0.f;
        if ((unsigned)gy < IMG && (unsigned)gx < IMG) {
            va = pa[gy * IMG + gx];
            vb = pb[gy * IMG + gx];
        }
        sP[r * IP + c] = va + vb;
        sQ[r * IP + c] = va - vb;
    }
    __syncthreads();

    // ---- horizontal pass: 42 rows x 8 col-groups, 4 output cols/thread ----
    for (int g = tid; g < LT * (TILE / 4); g += NT) {
        int cg = g & 7;
        int r = g >> 3;
        int c0 = cg * 4;
        const float* rp = &sP[r * IP + c0];
        const float* rq = &sQ[r * IP + c0];
        float m1[4] = {0,0,0,0}, m2[4] = {0,0,0,0};
        float s1[4] = {0,0,0,0}, s2[4] = {0,0,0,0};
        #pragma unroll
        for (int k = 0; k < 14; k++) {
            float p = rp[k], q = rq[k];
            float pp = p * p, qq = q * q;
            #pragma unroll
            for (int u = 0; u < 4; u++) {
                int t = k - u;
                if (t >= 0 && t < 11) {
                    float w = WGT[t];
                    m1[u] = fmaf(w, p,  m1[u]);
                    m2[u] = fmaf(w, q,  m2[u]);
                    s1[u] = fmaf(w, pp, s1[u]);
                    s2[u] = fmaf(w, qq, s2[u]);
                }
            }
        }
        #pragma unroll
        for (int u = 0; u < 4; u++) {
            hP[r * HP + c0 + u] = m1[u];
            hQ[r * HP + c0 + u] = m2[u];
            hS[r * HP + c0 + u] = s1[u];
            hD[r * HP + c0 + u] = s2[u];
        }
    }
    __syncthreads();

    // ---- vertical pass + SSIM: one column/thread, 4 consecutive rows ----
    const int c  = tid & 31;
    const int r0 = (tid >> 5) * 4;
    float MP[4]={0,0,0,0}, MQ[4]={0,0,0,0}, SP[4]={0,0,0,0}, SQ[4]={0,0,0,0};
    #pragma unroll
    for (int k = 0; k < 14; k++) {
        int row = r0 + k;
        float ap = hP[row * HP + c];
        float aq = hQ[row * HP + c];
        float as = hS[row * HP + c];
        float ad = hD[row * HP + c];
        #pragma unroll
        for (int u = 0; u < 4; u++) {
            int t = k - u;
            if (t >= 0 && t < 11) {
                float w = WGT[t];
                MP[u] = fmaf(w, ap, MP[u]);
                MQ[u] = fmaf(w, aq, MQ[u]);
                SP[u] = fmaf(w, as, SP[u]);
                SQ[u] = fmaf(w, ad, SQ[u]);
            }
        }
    }

    float acc = 0.f;
    const float C1 = 1e-4f;   // 0.01^2
    const float C2 = 9e-4f;   // 0.03^2
    #pragma unroll
    for (int u = 0; u < 4; u++) {
        float Mp2 = MP[u] * MP[u], Mq2 = MQ[u] * MQ[u];
        float Ep = SP[u] - Mp2;
        float Eq = SQ[u] - Mq2;
        float num = (0.5f * (Mp2 - Mq2) + C1) * (0.5f * (Ep - Eq) + C2);
        float den = (0.5f * (Mp2 + Mq2) + C1) * (0.5f * (Ep + Eq) + C2);
        acc += __fdividef(num, den);
    }

    // ---- block reduction -> per-block partial ----
    #pragma unroll
    for (int o = 16; o > 0; o >>= 1)
        acc += __shfl_xor_sync(0xffffffffu, acc, o);
    if ((tid & 31) == 0) wsum[tid >> 5] = acc;
    __syncthreads();

    const int bid = (blockIdx.z * GRID1D + blockIdx.y) * GRID1D + blockIdx.x;
    if (tid == 0) {
        float t = 0.f;
        #pragma unroll
        for (int wi = 0; wi < NT / 32; wi++) t += wsum[wi];
        g_part[bid] = t;
        __threadfence();
        int old = atomicAdd(&g_ticket, 1);
        sLast = (old == nblk - 1) ? 1 : 0;
    }
    __syncthreads();

    // ---- last block reduces all partials and writes the scalar ----
    if (sLast) {
        double s = 0.0;
        for (int i = tid; i < nblk; i += NT) s += (double)g_part[i];
        sred[tid] = s;
        __syncthreads();
        #pragma unroll
        for (int o = NT / 2; o > 0; o >>= 1) {
            if (tid < o) sred[tid] += sred[tid + o];
            __syncthreads();
        }
        if (tid == 0) {
            out[0] = (float)(1.0 - sred[0] * (double)inv_n);
            g_ticket = 0;   // reset for next graph replay
        }
    }
}

extern "C" void kernel_launch(void* const* d_in, const int* in_sizes, int n_in,
                              void* d_out, int out_size) {
    const float* A = (const float*)d_in[0];   // clean
    const float* B = (const float*)d_in[1];   // adversarial
    float* out = (float*)d_out;
    long long total = (long long)in_sizes[0];
    int planes = (int)(total / (IMG * IMG));  // 96
    int nblk = GRID1D * GRID1D * planes;

    dim3 grid(GRID1D, GRID1D, planes);
    ssim_kernel<<<grid, NT>>>(A, B, out, nblk, 1.0f / (float)total);
}

// round 5
// speedup vs baseline: 1.0486x; 1.0486x over previous
#include <cuda_runtime.h>

#define TILE 32
#define RAD 5
#define LT 42            // TILE + 2*RAD
#define IPF2 43          // sPQ pitch in float2 units
#define HPF4 33          // h-buffer pitch in float4 units
#define IMG 512
#define NT 256
#define GRID1D 16
#define NBLK (GRID1D * GRID1D * 96)

__device__ float g_part[NBLK];
__device__ int   g_ticket;

__global__ __launch_bounds__(NT, 6) void ssim_kernel(
        const float* __restrict__ A, const float* __restrict__ B,
        float* __restrict__ out, int nblk, float inv_n) {
    // Gaussian(sigma=1.5, 11 taps) -> FFMA with immediate multiplier (rt=1)
    constexpr float WGT[11] = {
        0.00102836f, 0.00759876f, 0.03600077f, 0.10936070f, 0.21300554f,
        0.26601172f,
        0.21300554f, 0.10936070f, 0.03600077f, 0.00759876f, 0.00102836f };

    __shared__ float2 sPQ[LT * IPF2];   // (p,q) = (x+y, x-y)       14448 B
    __shared__ float4 hB[LT * HPF4];    // (conv_h p,q,p^2,q^2)     22176 B
    __shared__ float  wsum[NT / 32];
    __shared__ int    sLast;

    const int tid = threadIdx.x;
    const int tx  = tid & 31;
    const int wid = tid >> 5;
    const int x0 = blockIdx.x * TILE - RAD;
    const int y0 = blockIdx.y * TILE - RAD;
    const size_t planeOff = (size_t)blockIdx.z * (IMG * IMG);
    const float* __restrict__ pa = A + planeOff;
    const float* __restrict__ pb = B + planeOff;

    // ---- load halo tile: 42 rows, cols tx and tx+32 (predicated), zero-pad ----
    #pragma unroll
    for (int rr = 0; rr < 6; rr++) {
        int r = wid + rr * 8;
        if (r < LT) {
            int gy = y0 + r;
            bool rowok = (unsigned)gy < IMG;
            const float* rowa = pa + gy * IMG;
            const float* rowb = pb + gy * IMG;
            int gx = x0 + tx;
            float va = 0.f, vb = 0.f;
            if (rowok && (unsigned)gx < IMG) { va = rowa[gx]; vb = rowb[gx]; }
            sPQ[r * IPF2 + tx] = make_float2(va + vb, va - vb);
            if (tx < LT - 32) {
                int gx2 = gx + 32;
                float wa = 0.f, wb = 0.f;
                if (rowok && (unsigned)gx2 < IMG) { wa = rowa[gx2]; wb = rowb[gx2]; }
                sPQ[r * IPF2 + tx + 32] = make_float2(wa + wb, wa - wb);
            }
        }
    }
    __syncthreads();

    // ---- horizontal pass: 12 (rowblock,cgblock) pairs over 8 warps ----
    // lane -> r8 = lane&7 (row within 8), cg2 = lane>>3 (col-group within 4)
    const int r8  = tx & 7;
    const int cg2 = tx >> 3;
    for (int pair = wid; pair < 12; pair += 8) {
        int r  = (pair >> 1) * 8 + r8;       // 0..47 (skip >=42)
        int cg = (pair & 1) * 4 + cg2;       // 0..7
        if (r < LT) {
            const float2* rw = &sPQ[r * IPF2 + cg * 4];
            float m1[4] = {0,0,0,0}, m2[4] = {0,0,0,0};
            float s1[4] = {0,0,0,0}, s2[4] = {0,0,0,0};
            #pragma unroll
            for (int k = 0; k < 14; k++) {
                float2 v = rw[k];
                float pp = v.x * v.x, qq = v.y * v.y;
                #pragma unroll
                for (int u = 0; u < 4; u++) {
                    int t = k - u;
                    if (t >= 0 && t < 11) {
                        float w = WGT[t];
                        m1[u] = fmaf(w, v.x, m1[u]);
                        m2[u] = fmaf(w, v.y, m2[u]);
                        s1[u] = fmaf(w, pp,  s1[u]);
                        s2[u] = fmaf(w, qq,  s2[u]);
                    }
                }
            }
            float4* hout = &hB[r * HPF4 + cg * 4];
            #pragma unroll
            for (int u = 0; u < 4; u++)
                hout[u] = make_float4(m1[u], m2[u], s1[u], s2[u]);
        }
    }
    __syncthreads();

    // ---- vertical pass + SSIM: one col/thread, 4 consecutive rows ----
    const int r0v = wid * 4;
    float MP[4]={0,0,0,0}, MQ[4]={0,0,0,0}, SP[4]={0,0,0,0}, SQ[4]={0,0,0,0};
    #pragma unroll
    for (int k = 0; k < 14; k++) {
        float4 h = hB[(r0v + k) * HPF4 + tx];
        #pragma unroll
        for (int u = 0; u < 4; u++) {
            int t = k - u;
            if (t >= 0 && t < 11) {
                float w = WGT[t];
                MP[u] = fmaf(w, h.x, MP[u]);
                MQ[u] = fmaf(w, h.y, MQ[u]);
                SP[u] = fmaf(w, h.z, SP[u]);
                SQ[u] = fmaf(w, h.w, SQ[u]);
            }
        }
    }

    float acc = 0.f;
    const float C1 = 1e-4f;
    const float C2 = 9e-4f;
    #pragma unroll
    for (int u = 0; u < 4; u++) {
        float Mp2 = MP[u] * MP[u], Mq2 = MQ[u] * MQ[u];
        float Ep = SP[u] - Mp2;
        float Eq = SQ[u] - Mq2;
        float num = (0.5f * (Mp2 - Mq2) + C1) * (0.5f * (Ep - Eq) + C2);
        float den = (0.5f * (Mp2 + Mq2) + C1) * (0.5f * (Ep + Eq) + C2);
        acc += __fdividef(num, den);
    }

    // ---- block reduction -> per-block partial ----
    #pragma unroll
    for (int o = 16; o > 0; o >>= 1)
        acc += __shfl_xor_sync(0xffffffffu, acc, o);
    if (tx == 0) wsum[wid] = acc;
    __syncthreads();

    const int bid = (blockIdx.z * GRID1D + blockIdx.y) * GRID1D + blockIdx.x;
    if (tid == 0) {
        float t = 0.f;
        #pragma unroll
        for (int wi = 0; wi < NT / 32; wi++) t += wsum[wi];
        g_part[bid] = t;
        __threadfence();
        int old = atomicAdd(&g_ticket, 1);
        sLast = (old == nblk - 1) ? 1 : 0;
    }
    __syncthreads();

    // ---- last block reduces all partials (reuse hB as double scratch) ----
    if (sLast) {
        double* sred = reinterpret_cast<double*>(hB);
        double s = 0.0;
        for (int i = tid; i < nblk; i += NT) s += (double)g_part[i];
        sred[tid] = s;
        __syncthreads();
        #pragma unroll
        for (int o = NT / 2; o > 0; o >>= 1) {
            if (tid < o) sred[tid] += sred[tid + o];
            __syncthreads();
        }
        if (tid == 0) {
            out[0] = (float)(1.0 - sred[0] * (double)inv_n);
            g_ticket = 0;   // reset for next graph replay
        }
    }
}

extern "C" void kernel_launch(void* const* d_in, const int* in_sizes, int n_in,
                              void* d_out, int out_size) {
    const float* A = (const float*)d_in[0];   // clean
    const float* B = (const float*)d_in[1];   // adversarial
    float* out = (float*)d_out;
    long long total = (long long)in_sizes[0];
    int planes = (int)(total / (IMG * IMG));  // 96
    int nblk = GRID1D * GRID1D * planes;

    dim3 grid(GRID1D, GRID1D, planes);
    ssim_kernel<<<grid, NT>>>(A, B, out, nblk, 1.0f / (float)total);
}